// round 1
// baseline (speedup 1.0000x reference)
#include <cuda_runtime.h>
#include <cuda_bf16.h>
#include <cstdint>

// Problem constants
#define Bsz 2
#define Sl  2048
#define Dm  768
#define Iw  1536
#define Nst 16
#define Rr  48
#define Kc  4
#define Ms  (Bsz * Sl)          // 4096 rows
#define TWO_I (2 * Iw)          // 3072

// ---------------------------------------------------------------------------
// Scratch buffers (device globals; allocation inside kernel_launch is banned)
// ---------------------------------------------------------------------------
__device__ float g_proj[(size_t)Ms * TWO_I];   // [B,S,2I]  hidden|gate
__device__ float g_h   [(size_t)Ms * Iw];      // [B,S,I]   conv+silu output
__device__ float g_ssm [(size_t)Ms * (Rr + 2 * Nst)];  // [B,S,80] ts|Bm|Cm
__device__ float g_dt  [(size_t)Ms * Iw];      // [B,S,I]   softplus dt (alpha applied)
__device__ float g_y   [(size_t)Ms * Iw];      // [B,S,I]   scan output (gated)

// ---------------------------------------------------------------------------
// Generic tiled SGEMM:  C[m,n] = sum_k A[m*lda + k] * W[n*K + k]
// EPI == 0 : plain store
// EPI == 1 : v = softplus(v + bias[n]); if (m % S == S-1) v *= lastscale[n]
// ---------------------------------------------------------------------------
template<int BM, int BN, int BK, int TM, int TN, int EPI>
__global__ __launch_bounds__(256)
void sgemm_nt(const float* __restrict__ A, const float* __restrict__ W,
              float* __restrict__ C, int M, int N, int K, int lda,
              const float* __restrict__ bias,
              const float* __restrict__ lastscale)
{
    constexpr int NT = (BM / TM) * (BN / TN);
    static_assert(NT == 256, "need 256 threads");
    constexpr int LA = (BM * BK) / (4 * NT);   // float4 loads of A per thread
    constexpr int LB = (BN * BK) / (4 * NT);
    static_assert(LA >= 1 && LB >= 1, "tile too small");

    __shared__ __align__(16) float As[BK][BM];
    __shared__ __align__(16) float Bs[BK][BN];

    const int tid = threadIdx.x;
    const int bm = blockIdx.y * BM;
    const int bn = blockIdx.x * BN;
    const int tx = tid % (BN / TN);
    const int ty = tid / (BN / TN);

    float acc[TM][TN];
#pragma unroll
    for (int a = 0; a < TM; a++)
#pragma unroll
        for (int b = 0; b < TN; b++) acc[a][b] = 0.f;

    for (int k0 = 0; k0 < K; k0 += BK) {
        // load A tile
#pragma unroll
        for (int l = 0; l < LA; l++) {
            int v = tid + l * NT;
            int r = v / (BK / 4);
            int kq = (v % (BK / 4)) * 4;
            int grow = bm + r;
            float4 av = make_float4(0.f, 0.f, 0.f, 0.f);
            if (grow < M)
                av = *(const float4*)(A + (size_t)grow * lda + k0 + kq);
            As[kq + 0][r] = av.x; As[kq + 1][r] = av.y;
            As[kq + 2][r] = av.z; As[kq + 3][r] = av.w;
        }
        // load W tile
#pragma unroll
        for (int l = 0; l < LB; l++) {
            int v = tid + l * NT;
            int r = v / (BK / 4);
            int kq = (v % (BK / 4)) * 4;
            int gcol = bn + r;
            float4 wv = make_float4(0.f, 0.f, 0.f, 0.f);
            if (gcol < N)
                wv = *(const float4*)(W + (size_t)gcol * K + k0 + kq);
            Bs[kq + 0][r] = wv.x; Bs[kq + 1][r] = wv.y;
            Bs[kq + 2][r] = wv.z; Bs[kq + 3][r] = wv.w;
        }
        __syncthreads();

#pragma unroll
        for (int k = 0; k < BK; k++) {
            float ra[TM], rb[TN];
#pragma unroll
            for (int u = 0; u < TM / 4; u++)
                *(float4*)&ra[4 * u] = *(const float4*)&As[k][ty * TM + 4 * u];
#pragma unroll
            for (int u = 0; u < TN / 4; u++)
                *(float4*)&rb[4 * u] = *(const float4*)&Bs[k][tx * TN + 4 * u];
#pragma unroll
            for (int a = 0; a < TM; a++)
#pragma unroll
                for (int b = 0; b < TN; b++)
                    acc[a][b] = fmaf(ra[a], rb[b], acc[a][b]);
        }
        __syncthreads();
    }

    // store
#pragma unroll
    for (int a = 0; a < TM; a++) {
        int m = bm + ty * TM + a;
        if (m >= M) continue;
        bool last = ((m % Sl) == (Sl - 1));
#pragma unroll
        for (int b = 0; b < TN; b++) {
            int n = bn + tx * TN + b;
            if (n >= N) continue;
            float v = acc[a][b];
            if (EPI == 1) {
                v += bias[n];
                v = (v > 20.f) ? v : log1pf(__expf(v));
                if (last) v *= lastscale[n];
            }
            C[(size_t)m * N + n] = v;
        }
    }
}

// ---------------------------------------------------------------------------
// Causal depthwise conv1d (K=4) + bias + SiLU.
// hidden = first I columns of proj [B,S,2I]; output h [B,S,I].
// ---------------------------------------------------------------------------
__global__ __launch_bounds__(256)
void conv_silu_kernel(const float* __restrict__ proj,
                      const float* __restrict__ cw,
                      const float* __restrict__ cb,
                      float* __restrict__ h)
{
    const int bs = blockIdx.x;          // b*S + s
    const int s = bs & (Sl - 1);
    for (int i = threadIdx.x; i < Iw; i += 256) {
        float4 w = *(const float4*)(cw + (size_t)i * 4);
        float acc = cb[i];
        const float* base = proj + (size_t)bs * TWO_I + i;
        if (s >= 3) acc = fmaf(w.x, base[-(size_t)3 * TWO_I], acc);
        if (s >= 2) acc = fmaf(w.y, base[-(size_t)2 * TWO_I], acc);
        if (s >= 1) acc = fmaf(w.z, base[-(size_t)1 * TWO_I], acc);
        acc = fmaf(w.w, base[0], acc);
        float sig = __fdividef(1.f, 1.f + __expf(-acc));
        h[(size_t)bs * Iw + i] = acc * sig;
    }
}

// ---------------------------------------------------------------------------
// Selective scan. 16 lanes per (b,i) channel, one lane per state n.
// state = exp(A[i,n]*dt) * state + dt * B[b,s,n] * h[b,s,i]
// y     = sum_n state*C[b,s,n];  y = (y + h*D[i]) * silu(gate); fg on last s.
// ---------------------------------------------------------------------------
__global__ __launch_bounds__(256)
void scan_kernel(const float* __restrict__ dt,
                 const float* __restrict__ h,
                 const float* __restrict__ ssm,
                 const float* __restrict__ proj,
                 const float* __restrict__ A_log,
                 const float* __restrict__ Dv,
                 const float* __restrict__ fg,
                 float* __restrict__ y)
{
    const int gi = blockIdx.x * 16 + (threadIdx.x >> 4);   // 0 .. B*I-1
    const int lane = threadIdx.x & 15;                     // state index n
    const int b = gi / Iw;
    const int i = gi - b * Iw;

    const float An = -__expf(A_log[(size_t)i * Nst + lane]);
    const float Di = Dv[i];
    const float fgi = fg[i];
    float state = 0.f;

    const float* dt_p  = dt   + (size_t)b * Sl * Iw + i;
    const float* h_p   = h    + (size_t)b * Sl * Iw + i;
    const float* ssm_p = ssm  + (size_t)b * Sl * (Rr + 2 * Nst);
    const float* g_p   = proj + (size_t)b * Sl * TWO_I + Iw + i;
    float* y_p         = y    + (size_t)b * Sl * Iw + i;

    for (int s = 0; s < Sl; s++) {
        float dtv = dt_p[(size_t)s * Iw];
        float hv  = h_p [(size_t)s * Iw];
        const float* row = ssm_p + (size_t)s * (Rr + 2 * Nst);
        float Bv = row[Rr + lane];
        float Cv = row[Rr + Nst + lane];

        float dA = __expf(An * dtv);
        state = fmaf(dA, state, dtv * Bv * hv);

        float part = state * Cv;
        part += __shfl_xor_sync(0xffffffffu, part, 8);
        part += __shfl_xor_sync(0xffffffffu, part, 4);
        part += __shfl_xor_sync(0xffffffffu, part, 2);
        part += __shfl_xor_sync(0xffffffffu, part, 1);

        if (lane == 0) {
            float g = g_p[(size_t)s * TWO_I];
            float silu_g = g * __fdividef(1.f, 1.f + __expf(-g));
            float val = (part + hv * Di) * silu_g;
            if (s == Sl - 1) val *= fgi;
            y_p[(size_t)s * Iw] = val;
        }
    }
}

// ---------------------------------------------------------------------------
// Launch
// ---------------------------------------------------------------------------
extern "C" void kernel_launch(void* const* d_in, const int* in_sizes, int n_in,
                              void* d_out, int out_size)
{
    const float* x          = (const float*)d_in[0];
    const float* in_proj_w  = (const float*)d_in[1];
    const float* conv_w     = (const float*)d_in[2];
    const float* conv_b     = (const float*)d_in[3];
    const float* x_proj_w   = (const float*)d_in[4];
    const float* dt_proj_w  = (const float*)d_in[5];
    const float* dt_proj_b  = (const float*)d_in[6];
    const float* A_log      = (const float*)d_in[7];
    const float* Dv         = (const float*)d_in[8];
    const float* out_proj_w = (const float*)d_in[9];
    const float* alpha      = (const float*)d_in[10];
    const float* fg         = (const float*)d_in[11];
    float* out = (float*)d_out;

    float *proj, *h, *ssm, *dt, *y;
    cudaGetSymbolAddress((void**)&proj, g_proj);
    cudaGetSymbolAddress((void**)&h,    g_h);
    cudaGetSymbolAddress((void**)&ssm,  g_ssm);
    cudaGetSymbolAddress((void**)&dt,   g_dt);
    cudaGetSymbolAddress((void**)&y,    g_y);

    // 1) in_proj: [4096,768] x [3072,768]^T -> proj [4096,3072]
    sgemm_nt<128,128,16,8,8,0><<<dim3(TWO_I/128, Ms/128), 256>>>(
        x, in_proj_w, proj, Ms, TWO_I, Dm, Dm, nullptr, nullptr);

    // 2) causal depthwise conv + SiLU -> h [4096,1536]
    conv_silu_kernel<<<Ms, 256>>>(proj, conv_w, conv_b, h);

    // 3) x_proj: [4096,1536] x [80,1536]^T -> ssm [4096,80]
    sgemm_nt<64,64,16,4,4,0><<<dim3(2, Ms/64), 256>>>(
        h, x_proj_w, ssm, Ms, Rr + 2*Nst, Iw, Iw, nullptr, nullptr);

    // 4) dt_proj + softplus + alpha(last step): ts part of ssm (lda=80, K=48)
    sgemm_nt<64,64,16,4,4,1><<<dim3(Iw/64, Ms/64), 256>>>(
        ssm, dt_proj_w, dt, Ms, Iw, Rr, Rr + 2*Nst, dt_proj_b, alpha);

    // 5) selective scan -> y [4096,1536]
    scan_kernel<<<(Bsz * Iw) / 16, 256>>>(dt, h, ssm, proj, A_log, Dv, fg, y);

    // 6) out_proj: [4096,1536] x [768,1536]^T -> out [4096,768]
    sgemm_nt<128,128,16,8,8,0><<<dim3(Dm/128, Ms/128), 256>>>(
        y, out_proj_w, out, Ms, Dm, Iw, Iw, nullptr, nullptr);
}

// round 4
// speedup vs baseline: 1.3450x; 1.3450x over previous
#include <cuda_runtime.h>
#include <cuda_bf16.h>
#include <cstdint>

// Problem constants
#define Bsz 2
#define Sl  2048
#define Dm  768
#define Iw  1536
#define Nst 16
#define Rr  48
#define Ms  (Bsz * Sl)          // 4096 rows
#define TWO_I (2 * Iw)          // 3072

// ---------------------------------------------------------------------------
// Scratch (device globals)
// ---------------------------------------------------------------------------
__device__ float g_proj[(size_t)Ms * TWO_I];
__device__ float g_h   [(size_t)Ms * Iw];
__device__ float g_ssm [(size_t)Ms * (Rr + 2 * Nst)];
__device__ float g_dt  [(size_t)Ms * Iw];
__device__ float g_y   [(size_t)Ms * Iw];

__device__ __nv_bfloat16 g_xhi [(size_t)Ms * Dm],    g_xlo [(size_t)Ms * Dm];
__device__ __nv_bfloat16 g_w1hi[(size_t)TWO_I * Dm], g_w1lo[(size_t)TWO_I * Dm];
__device__ __nv_bfloat16 g_yhi [(size_t)Ms * Iw],    g_ylo [(size_t)Ms * Iw];
__device__ __nv_bfloat16 g_w2hi[(size_t)Dm * Iw],    g_w2lo[(size_t)Dm * Iw];

// ---------------------------------------------------------------------------
// Helpers
// ---------------------------------------------------------------------------
__device__ __forceinline__ uint32_t smem_u32(const void* p) {
    uint32_t a;
    asm("{ .reg .u64 t; cvta.to.shared.u64 t, %1; cvt.u32.u64 %0, t; }" : "=r"(a) : "l"(p));
    return a;
}
__device__ __forceinline__ void cp16(uint32_t saddr, const void* gsrc) {
    asm volatile("cp.async.cg.shared.global [%0], [%1], 16;" :: "r"(saddr), "l"(gsrc));
}
#define CP_COMMIT() asm volatile("cp.async.commit_group;" ::: "memory")
#define CP_WAIT(n)  asm volatile("cp.async.wait_group %0;" :: "n"(n) : "memory")

__device__ __forceinline__ void ldm_x4(uint32_t* r, uint32_t addr) {
    asm volatile("ldmatrix.sync.aligned.m8n8.x4.shared.b16 {%0,%1,%2,%3}, [%4];"
                 : "=r"(r[0]), "=r"(r[1]), "=r"(r[2]), "=r"(r[3]) : "r"(addr));
}
__device__ __forceinline__ void ldm_x2(uint32_t* r, uint32_t addr) {
    asm volatile("ldmatrix.sync.aligned.m8n8.x2.shared.b16 {%0,%1}, [%2];"
                 : "=r"(r[0]), "=r"(r[1]) : "r"(addr));
}
__device__ __forceinline__ void mma16816(float* c, const uint32_t* a, const uint32_t* b) {
    asm volatile("mma.sync.aligned.m16n8k16.row.col.f32.bf16.bf16.f32 "
                 "{%0,%1,%2,%3}, {%4,%5,%6,%7}, {%8,%9}, {%0,%1,%2,%3};"
                 : "+f"(c[0]), "+f"(c[1]), "+f"(c[2]), "+f"(c[3])
                 : "r"(a[0]), "r"(a[1]), "r"(a[2]), "r"(a[3]), "r"(b[0]), "r"(b[1]));
}

// ---------------------------------------------------------------------------
// HMMA bf16x3 GEMM: C[M,N] = (Ahi+Alo)[M,K] @ (Whi+Wlo)[N,K]^T  (drop lo*lo)
// 128x128 CTA tile, BK=32, 256 threads, 2-stage cp.async pipeline.
// Smem tiles padded to stride 40 bf16 (80B).
// ---------------------------------------------------------------------------
#define STRD 40
#define TILE_B (128 * STRD * 2)            // bytes per matrix tile (10240)
#define STAGE_B (4 * TILE_B)               // 4 matrices per stage (40960)
#define SMEM_B (2 * STAGE_B)               // 81920

__global__ __launch_bounds__(256)
void hmma_bf16x3(const __nv_bfloat16* __restrict__ Ahi, const __nv_bfloat16* __restrict__ Alo,
                 const __nv_bfloat16* __restrict__ Whi, const __nv_bfloat16* __restrict__ Wlo,
                 float* __restrict__ C, int M, int N, int K)
{
    extern __shared__ __align__(16) char smem[];
    const uint32_t sb = smem_u32(smem);
    const int tid = threadIdx.x;
    const int wid = tid >> 5, lane = tid & 31;
    const int warp_m = wid >> 2, warp_n = wid & 3;
    const int bm = blockIdx.y * 128, bn = blockIdx.x * 128;

    const __nv_bfloat16* gA[2] = {Ahi, Alo};
    const __nv_bfloat16* gW[2] = {Whi, Wlo};

    auto load_stage = [&](int st, int k0) {
#pragma unroll
        for (int l = 0; l < 8; l++) {
            int v = tid + l * 256;
            int mat = v >> 9;
            int row = (v >> 2) & 127;
            int c16 = v & 3;
            const __nv_bfloat16* src;
            if (mat < 2) src = gA[mat] + (size_t)(bm + row) * K + k0 + c16 * 8;
            else         src = gW[mat - 2] + (size_t)(bn + row) * K + k0 + c16 * 8;
            uint32_t dst = sb + st * STAGE_B + mat * TILE_B + (row * STRD + c16 * 8) * 2;
            cp16(dst, src);
        }
        CP_COMMIT();
    };

    float acc[4][4][4];
#pragma unroll
    for (int i = 0; i < 4; i++)
#pragma unroll
        for (int j = 0; j < 4; j++)
#pragma unroll
            for (int k = 0; k < 4; k++) acc[i][j][k] = 0.f;

    const int nch = K >> 5;
    load_stage(0, 0);

    // fragment address components (A: x4 non-trans; B: x2 non-trans)
    const int a_r = warp_m * 64 + (lane & 15);        // + mt*16
    const int a_k = (lane >> 4) * 8;                  // + kk*16
    const int b_r = warp_n * 32 + (lane & 7);         // + nt*8
    const int b_k = ((lane >> 3) & 1) * 8;            // + kk*16  (lanes 0-15 used)

    for (int ch = 0; ch < nch; ch++) {
        const int st = ch & 1;
        if (ch + 1 < nch) load_stage(st ^ 1, (ch + 1) << 5);
        if (ch + 1 < nch) { CP_WAIT(1); } else { CP_WAIT(0); }
        __syncthreads();

        const uint32_t aHiB = sb + st * STAGE_B;
        const uint32_t aLoB = aHiB + TILE_B;
        const uint32_t wHiB = aHiB + 2 * TILE_B;
        const uint32_t wLoB = aHiB + 3 * TILE_B;

#pragma unroll
        for (int kk = 0; kk < 2; kk++) {
            uint32_t ahi[4][4], bhi[4][2], tmp[4][4];
#pragma unroll
            for (int mt = 0; mt < 4; mt++)
                ldm_x4(ahi[mt], aHiB + ((a_r + mt * 16) * STRD + a_k + kk * 16) * 2);
#pragma unroll
            for (int nt = 0; nt < 4; nt++)
                ldm_x2(bhi[nt], wHiB + ((b_r + nt * 8) * STRD + b_k + kk * 16) * 2);
            // hi * hi
#pragma unroll
            for (int mt = 0; mt < 4; mt++)
#pragma unroll
                for (int nt = 0; nt < 4; nt++)
                    mma16816(acc[mt][nt], ahi[mt], bhi[nt]);
            // lo * hi
#pragma unroll
            for (int mt = 0; mt < 4; mt++)
                ldm_x4(tmp[mt], aLoB + ((a_r + mt * 16) * STRD + a_k + kk * 16) * 2);
#pragma unroll
            for (int mt = 0; mt < 4; mt++)
#pragma unroll
                for (int nt = 0; nt < 4; nt++)
                    mma16816(acc[mt][nt], tmp[mt], bhi[nt]);
            // hi * lo
            uint32_t blo[4][2];
#pragma unroll
            for (int nt = 0; nt < 4; nt++)
                ldm_x2(blo[nt], wLoB + ((b_r + nt * 8) * STRD + b_k + kk * 16) * 2);
#pragma unroll
            for (int mt = 0; mt < 4; mt++)
#pragma unroll
                for (int nt = 0; nt < 4; nt++)
                    mma16816(acc[mt][nt], ahi[mt], blo[nt]);
        }
        __syncthreads();
    }

    // epilogue: direct float2 stores
    const int er = bm + warp_m * 64 + (lane >> 2);
    const int ec = bn + warp_n * 32 + (lane & 3) * 2;
#pragma unroll
    for (int mt = 0; mt < 4; mt++)
#pragma unroll
        for (int nt = 0; nt < 4; nt++) {
            int r = er + mt * 16;
            int c = ec + nt * 8;
            *(float2*)&C[(size_t)r * N + c]       = make_float2(acc[mt][nt][0], acc[mt][nt][1]);
            *(float2*)&C[(size_t)(r + 8) * N + c] = make_float2(acc[mt][nt][2], acc[mt][nt][3]);
        }
}

// ---------------------------------------------------------------------------
// fp32 -> (hi, lo) bf16 split
// ---------------------------------------------------------------------------
__global__ __launch_bounds__(256)
void split_bf16(const float* __restrict__ in, __nv_bfloat16* __restrict__ hi,
                __nv_bfloat16* __restrict__ lo, int n4)
{
    int i = blockIdx.x * 256 + threadIdx.x;
    if (i >= n4) return;
    float4 v = ((const float4*)in)[i];
    __nv_bfloat16 h0 = __float2bfloat16(v.x), h1 = __float2bfloat16(v.y);
    __nv_bfloat16 h2 = __float2bfloat16(v.z), h3 = __float2bfloat16(v.w);
    __nv_bfloat162* hp = (__nv_bfloat162*)(hi + (size_t)i * 4);
    hp[0] = __nv_bfloat162(h0, h1);
    hp[1] = __nv_bfloat162(h2, h3);
    __nv_bfloat162* lp = (__nv_bfloat162*)(lo + (size_t)i * 4);
    lp[0] = __nv_bfloat162(__float2bfloat16(v.x - __bfloat162float(h0)),
                           __float2bfloat16(v.y - __bfloat162float(h1)));
    lp[1] = __nv_bfloat162(__float2bfloat16(v.z - __bfloat162float(h2)),
                           __float2bfloat16(v.w - __bfloat162float(h3)));
}

// ---------------------------------------------------------------------------
// fp32 tiled SGEMM (small GEMMs)
// ---------------------------------------------------------------------------
template<int BM, int BN, int BK, int TM, int TN, int EPI>
__global__ __launch_bounds__(256)
void sgemm_nt(const float* __restrict__ A, const float* __restrict__ W,
              float* __restrict__ C, int M, int N, int K, int lda,
              const float* __restrict__ bias,
              const float* __restrict__ lastscale)
{
    constexpr int NT = (BM / TM) * (BN / TN);
    static_assert(NT == 256, "need 256 threads");
    constexpr int LA = (BM * BK) / (4 * NT);
    constexpr int LB = (BN * BK) / (4 * NT);

    __shared__ __align__(16) float As[BK][BM];
    __shared__ __align__(16) float Bs[BK][BN];

    const int tid = threadIdx.x;
    const int bm = blockIdx.y * BM;
    const int bn = blockIdx.x * BN;
    const int tx = tid % (BN / TN);
    const int ty = tid / (BN / TN);

    float acc[TM][TN];
#pragma unroll
    for (int a = 0; a < TM; a++)
#pragma unroll
        for (int b = 0; b < TN; b++) acc[a][b] = 0.f;

    for (int k0 = 0; k0 < K; k0 += BK) {
#pragma unroll
        for (int l = 0; l < LA; l++) {
            int v = tid + l * NT;
            int r = v / (BK / 4);
            int kq = (v % (BK / 4)) * 4;
            int grow = bm + r;
            float4 av = make_float4(0.f, 0.f, 0.f, 0.f);
            if (grow < M)
                av = *(const float4*)(A + (size_t)grow * lda + k0 + kq);
            As[kq + 0][r] = av.x; As[kq + 1][r] = av.y;
            As[kq + 2][r] = av.z; As[kq + 3][r] = av.w;
        }
#pragma unroll
        for (int l = 0; l < LB; l++) {
            int v = tid + l * NT;
            int r = v / (BK / 4);
            int kq = (v % (BK / 4)) * 4;
            int gcol = bn + r;
            float4 wv = make_float4(0.f, 0.f, 0.f, 0.f);
            if (gcol < N)
                wv = *(const float4*)(W + (size_t)gcol * K + k0 + kq);
            Bs[kq + 0][r] = wv.x; Bs[kq + 1][r] = wv.y;
            Bs[kq + 2][r] = wv.z; Bs[kq + 3][r] = wv.w;
        }
        __syncthreads();

#pragma unroll
        for (int k = 0; k < BK; k++) {
            float ra[TM], rb[TN];
#pragma unroll
            for (int u = 0; u < TM / 4; u++)
                *(float4*)&ra[4 * u] = *(const float4*)&As[k][ty * TM + 4 * u];
#pragma unroll
            for (int u = 0; u < TN / 4; u++)
                *(float4*)&rb[4 * u] = *(const float4*)&Bs[k][tx * TN + 4 * u];
#pragma unroll
            for (int a = 0; a < TM; a++)
#pragma unroll
                for (int b = 0; b < TN; b++)
                    acc[a][b] = fmaf(ra[a], rb[b], acc[a][b]);
        }
        __syncthreads();
    }

#pragma unroll
    for (int a = 0; a < TM; a++) {
        int m = bm + ty * TM + a;
        if (m >= M) continue;
        bool last = ((m % Sl) == (Sl - 1));
#pragma unroll
        for (int b = 0; b < TN; b++) {
            int n = bn + tx * TN + b;
            if (n >= N) continue;
            float v = acc[a][b];
            if (EPI == 1) {
                v += bias[n];
                v = (v > 20.f) ? v : log1pf(__expf(v));
                if (last) v *= lastscale[n];
            }
            C[(size_t)m * N + n] = v;
        }
    }
}

// ---------------------------------------------------------------------------
// Causal depthwise conv1d (K=4) + bias + SiLU
// ---------------------------------------------------------------------------
__global__ __launch_bounds__(256)
void conv_silu_kernel(const float* __restrict__ proj,
                      const float* __restrict__ cw,
                      const float* __restrict__ cb,
                      float* __restrict__ h)
{
    const int bs = blockIdx.x;
    const int s = bs & (Sl - 1);
    for (int i = threadIdx.x; i < Iw; i += 256) {
        float4 w = *(const float4*)(cw + (size_t)i * 4);
        float acc = cb[i];
        const float* base = proj + (size_t)bs * TWO_I + i;
        if (s >= 3) acc = fmaf(w.x, base[-(size_t)3 * TWO_I], acc);
        if (s >= 2) acc = fmaf(w.y, base[-(size_t)2 * TWO_I], acc);
        if (s >= 1) acc = fmaf(w.z, base[-(size_t)1 * TWO_I], acc);
        acc = fmaf(w.w, base[0], acc);
        float sig = __fdividef(1.f, 1.f + __expf(-acc));
        h[(size_t)bs * Iw + i] = acc * sig;
    }
}

// ---------------------------------------------------------------------------
// Selective scan (16 lanes per channel, lane = state index)
// ---------------------------------------------------------------------------
__global__ __launch_bounds__(256)
void scan_kernel(const float* __restrict__ dt,
                 const float* __restrict__ h,
                 const float* __restrict__ ssm,
                 const float* __restrict__ proj,
                 const float* __restrict__ A_log,
                 const float* __restrict__ Dv,
                 const float* __restrict__ fg,
                 float* __restrict__ y)
{
    const int gi = blockIdx.x * 16 + (threadIdx.x >> 4);
    const int lane = threadIdx.x & 15;
    const int b = gi / Iw;
    const int i = gi - b * Iw;

    const float An = -__expf(A_log[(size_t)i * Nst + lane]);
    const float Di = Dv[i];
    const float fgi = fg[i];
    float state = 0.f;

    const float* dt_p  = dt   + (size_t)b * Sl * Iw + i;
    const float* h_p   = h    + (size_t)b * Sl * Iw + i;
    const float* ssm_p = ssm  + (size_t)b * Sl * (Rr + 2 * Nst);
    const float* g_p   = proj + (size_t)b * Sl * TWO_I + Iw + i;
    float* y_p         = y    + (size_t)b * Sl * Iw + i;

    for (int s = 0; s < Sl; s++) {
        float dtv = dt_p[(size_t)s * Iw];
        float hv  = h_p [(size_t)s * Iw];
        const float* row = ssm_p + (size_t)s * (Rr + 2 * Nst);
        float Bv = row[Rr + lane];
        float Cv = row[Rr + Nst + lane];

        float dA = __expf(An * dtv);
        state = fmaf(dA, state, dtv * Bv * hv);

        float part = state * Cv;
        part += __shfl_xor_sync(0xffffffffu, part, 8);
        part += __shfl_xor_sync(0xffffffffu, part, 4);
        part += __shfl_xor_sync(0xffffffffu, part, 2);
        part += __shfl_xor_sync(0xffffffffu, part, 1);

        if (lane == 0) {
            float g = g_p[(size_t)s * TWO_I];
            float silu_g = g * __fdividef(1.f, 1.f + __expf(-g));
            float val = (part + hv * Di) * silu_g;
            if (s == Sl - 1) val *= fgi;
            y_p[(size_t)s * Iw] = val;
        }
    }
}

// ---------------------------------------------------------------------------
// Launch
// ---------------------------------------------------------------------------
extern "C" void kernel_launch(void* const* d_in, const int* in_sizes, int n_in,
                              void* d_out, int out_size)
{
    const float* x          = (const float*)d_in[0];
    const float* in_proj_w  = (const float*)d_in[1];
    const float* conv_w     = (const float*)d_in[2];
    const float* conv_b     = (const float*)d_in[3];
    const float* x_proj_w   = (const float*)d_in[4];
    const float* dt_proj_w  = (const float*)d_in[5];
    const float* dt_proj_b  = (const float*)d_in[6];
    const float* A_log      = (const float*)d_in[7];
    const float* Dv         = (const float*)d_in[8];
    const float* out_proj_w = (const float*)d_in[9];
    const float* alpha      = (const float*)d_in[10];
    const float* fg         = (const float*)d_in[11];
    float* out = (float*)d_out;

    float *proj, *h, *ssm, *dt, *y;
    cudaGetSymbolAddress((void**)&proj, g_proj);
    cudaGetSymbolAddress((void**)&h,    g_h);
    cudaGetSymbolAddress((void**)&ssm,  g_ssm);
    cudaGetSymbolAddress((void**)&dt,   g_dt);
    cudaGetSymbolAddress((void**)&y,    g_y);

    __nv_bfloat16 *xhi, *xlo, *w1hi, *w1lo, *yhi, *ylo, *w2hi, *w2lo;
    cudaGetSymbolAddress((void**)&xhi,  g_xhi);
    cudaGetSymbolAddress((void**)&xlo,  g_xlo);
    cudaGetSymbolAddress((void**)&w1hi, g_w1hi);
    cudaGetSymbolAddress((void**)&w1lo, g_w1lo);
    cudaGetSymbolAddress((void**)&yhi,  g_yhi);
    cudaGetSymbolAddress((void**)&ylo,  g_ylo);
    cudaGetSymbolAddress((void**)&w2hi, g_w2hi);
    cudaGetSymbolAddress((void**)&w2lo, g_w2lo);

    cudaFuncSetAttribute(hmma_bf16x3, cudaFuncAttributeMaxDynamicSharedMemorySize, SMEM_B);

    // split inputs for in_proj
    {
        int n4 = (Ms * Dm) / 4;
        split_bf16<<<(n4 + 255) / 256, 256>>>(x, xhi, xlo, n4);
        n4 = (TWO_I * Dm) / 4;
        split_bf16<<<(n4 + 255) / 256, 256>>>(in_proj_w, w1hi, w1lo, n4);
    }

    // 1) in_proj (HMMA): proj[4096,3072] = x @ in_proj_w^T
    hmma_bf16x3<<<dim3(TWO_I / 128, Ms / 128), 256, SMEM_B>>>(
        xhi, xlo, w1hi, w1lo, proj, Ms, TWO_I, Dm);

    // 2) conv + SiLU
    conv_silu_kernel<<<Ms, 256>>>(proj, conv_w, conv_b, h);

    // 3) x_proj (fp32)
    sgemm_nt<64,64,16,4,4,0><<<dim3(2, Ms/64), 256>>>(
        h, x_proj_w, ssm, Ms, Rr + 2*Nst, Iw, Iw, nullptr, nullptr);

    // 4) dt_proj + softplus + alpha
    sgemm_nt<64,64,16,4,4,1><<<dim3(Iw/64, Ms/64), 256>>>(
        ssm, dt_proj_w, dt, Ms, Iw, Rr, Rr + 2*Nst, dt_proj_b, alpha);

    // 5) scan
    scan_kernel<<<(Bsz * Iw) / 16, 256>>>(dt, h, ssm, proj, A_log, Dv, fg, y);

    // split y and out_proj_w
    {
        int n4 = (Ms * Iw) / 4;
        split_bf16<<<(n4 + 255) / 256, 256>>>(y, yhi, ylo, n4);
        n4 = (Dm * Iw) / 4;
        split_bf16<<<(n4 + 255) / 256, 256>>>(out_proj_w, w2hi, w2lo, n4);
    }

    // 6) out_proj (HMMA): out[4096,768] = y @ out_proj_w^T
    hmma_bf16x3<<<dim3(Dm / 128, Ms / 128), 256, SMEM_B>>>(
        yhi, ylo, w2hi, w2lo, out, Ms, Dm, Iw);
}

// round 5
// speedup vs baseline: 2.8349x; 2.1077x over previous
#include <cuda_runtime.h>
#include <cuda_bf16.h>
#include <cstdint>

// Problem constants
#define Bsz 2
#define Sl  2048
#define Dm  768
#define Iw  1536
#define Nst 16
#define Rr  48
#define Ms  (Bsz * Sl)          // 4096 rows
#define TWO_I (2 * Iw)          // 3072

// ---------------------------------------------------------------------------
// Scratch (device globals)
// ---------------------------------------------------------------------------
__device__ float g_proj[(size_t)Ms * TWO_I];
__device__ float g_h   [(size_t)Ms * Iw];
__device__ float g_ssm [(size_t)Ms * (Rr + 2 * Nst)];
__device__ float g_dt  [(size_t)Ms * Iw];

__device__ __nv_bfloat16 g_xhi [(size_t)Ms * Dm],    g_xlo [(size_t)Ms * Dm];
__device__ __nv_bfloat16 g_w1hi[(size_t)TWO_I * Dm], g_w1lo[(size_t)TWO_I * Dm];
__device__ __nv_bfloat16 g_yhi [(size_t)Ms * Iw],    g_ylo [(size_t)Ms * Iw];
__device__ __nv_bfloat16 g_w2hi[(size_t)Dm * Iw],    g_w2lo[(size_t)Dm * Iw];

// ---------------------------------------------------------------------------
// Helpers
// ---------------------------------------------------------------------------
__device__ __forceinline__ uint32_t smem_u32(const void* p) {
    uint32_t a;
    asm("{ .reg .u64 t; cvta.to.shared.u64 t, %1; cvt.u32.u64 %0, t; }" : "=r"(a) : "l"(p));
    return a;
}
__device__ __forceinline__ void cp16(uint32_t saddr, const void* gsrc) {
    asm volatile("cp.async.cg.shared.global [%0], [%1], 16;" :: "r"(saddr), "l"(gsrc));
}
#define CP_COMMIT() asm volatile("cp.async.commit_group;" ::: "memory")
#define CP_WAIT(n)  asm volatile("cp.async.wait_group %0;" :: "n"(n) : "memory")

__device__ __forceinline__ void ldm_x4(uint32_t* r, uint32_t addr) {
    asm volatile("ldmatrix.sync.aligned.m8n8.x4.shared.b16 {%0,%1,%2,%3}, [%4];"
                 : "=r"(r[0]), "=r"(r[1]), "=r"(r[2]), "=r"(r[3]) : "r"(addr));
}
__device__ __forceinline__ void ldm_x2(uint32_t* r, uint32_t addr) {
    asm volatile("ldmatrix.sync.aligned.m8n8.x2.shared.b16 {%0,%1}, [%2];"
                 : "=r"(r[0]), "=r"(r[1]) : "r"(addr));
}
__device__ __forceinline__ void mma16816(float* c, const uint32_t* a, const uint32_t* b) {
    asm volatile("mma.sync.aligned.m16n8k16.row.col.f32.bf16.bf16.f32 "
                 "{%0,%1,%2,%3}, {%4,%5,%6,%7}, {%8,%9}, {%0,%1,%2,%3};"
                 : "+f"(c[0]), "+f"(c[1]), "+f"(c[2]), "+f"(c[3])
                 : "r"(a[0]), "r"(a[1]), "r"(a[2]), "r"(a[3]), "r"(b[0]), "r"(b[1]));
}

// ---------------------------------------------------------------------------
// HMMA bf16x3 GEMM (unchanged from R4): C = (Ahi+Alo) @ (Whi+Wlo)^T, drop lo*lo
// ---------------------------------------------------------------------------
#define STRD 40
#define TILE_B (128 * STRD * 2)
#define STAGE_B (4 * TILE_B)
#define SMEM_B (2 * STAGE_B)

__global__ __launch_bounds__(256)
void hmma_bf16x3(const __nv_bfloat16* __restrict__ Ahi, const __nv_bfloat16* __restrict__ Alo,
                 const __nv_bfloat16* __restrict__ Whi, const __nv_bfloat16* __restrict__ Wlo,
                 float* __restrict__ C, int M, int N, int K)
{
    extern __shared__ __align__(16) char smem[];
    const uint32_t sb = smem_u32(smem);
    const int tid = threadIdx.x;
    const int wid = tid >> 5, lane = tid & 31;
    const int warp_m = wid >> 2, warp_n = wid & 3;
    const int bm = blockIdx.y * 128, bn = blockIdx.x * 128;

    const __nv_bfloat16* gA[2] = {Ahi, Alo};
    const __nv_bfloat16* gW[2] = {Whi, Wlo};

    auto load_stage = [&](int st, int k0) {
#pragma unroll
        for (int l = 0; l < 8; l++) {
            int v = tid + l * 256;
            int mat = v >> 9;
            int row = (v >> 2) & 127;
            int c16 = v & 3;
            const __nv_bfloat16* src;
            if (mat < 2) src = gA[mat] + (size_t)(bm + row) * K + k0 + c16 * 8;
            else         src = gW[mat - 2] + (size_t)(bn + row) * K + k0 + c16 * 8;
            uint32_t dst = sb + st * STAGE_B + mat * TILE_B + (row * STRD + c16 * 8) * 2;
            cp16(dst, src);
        }
        CP_COMMIT();
    };

    float acc[4][4][4];
#pragma unroll
    for (int i = 0; i < 4; i++)
#pragma unroll
        for (int j = 0; j < 4; j++)
#pragma unroll
            for (int k = 0; k < 4; k++) acc[i][j][k] = 0.f;

    const int nch = K >> 5;
    load_stage(0, 0);

    const int a_r = warp_m * 64 + (lane & 15);
    const int a_k = (lane >> 4) * 8;
    const int b_r = warp_n * 32 + (lane & 7);
    const int b_k = ((lane >> 3) & 1) * 8;

    for (int ch = 0; ch < nch; ch++) {
        const int st = ch & 1;
        if (ch + 1 < nch) load_stage(st ^ 1, (ch + 1) << 5);
        if (ch + 1 < nch) { CP_WAIT(1); } else { CP_WAIT(0); }
        __syncthreads();

        const uint32_t aHiB = sb + st * STAGE_B;
        const uint32_t aLoB = aHiB + TILE_B;
        const uint32_t wHiB = aHiB + 2 * TILE_B;
        const uint32_t wLoB = aHiB + 3 * TILE_B;

#pragma unroll
        for (int kk = 0; kk < 2; kk++) {
            uint32_t ahi[4][4], bhi[4][2], tmp[4][4];
#pragma unroll
            for (int mt = 0; mt < 4; mt++)
                ldm_x4(ahi[mt], aHiB + ((a_r + mt * 16) * STRD + a_k + kk * 16) * 2);
#pragma unroll
            for (int nt = 0; nt < 4; nt++)
                ldm_x2(bhi[nt], wHiB + ((b_r + nt * 8) * STRD + b_k + kk * 16) * 2);
#pragma unroll
            for (int mt = 0; mt < 4; mt++)
#pragma unroll
                for (int nt = 0; nt < 4; nt++)
                    mma16816(acc[mt][nt], ahi[mt], bhi[nt]);
#pragma unroll
            for (int mt = 0; mt < 4; mt++)
                ldm_x4(tmp[mt], aLoB + ((a_r + mt * 16) * STRD + a_k + kk * 16) * 2);
#pragma unroll
            for (int mt = 0; mt < 4; mt++)
#pragma unroll
                for (int nt = 0; nt < 4; nt++)
                    mma16816(acc[mt][nt], tmp[mt], bhi[nt]);
            uint32_t blo[4][2];
#pragma unroll
            for (int nt = 0; nt < 4; nt++)
                ldm_x2(blo[nt], wLoB + ((b_r + nt * 8) * STRD + b_k + kk * 16) * 2);
#pragma unroll
            for (int mt = 0; mt < 4; mt++)
#pragma unroll
                for (int nt = 0; nt < 4; nt++)
                    mma16816(acc[mt][nt], ahi[mt], blo[nt]);
        }
        __syncthreads();
    }

    const int er = bm + warp_m * 64 + (lane >> 2);
    const int ec = bn + warp_n * 32 + (lane & 3) * 2;
#pragma unroll
    for (int mt = 0; mt < 4; mt++)
#pragma unroll
        for (int nt = 0; nt < 4; nt++) {
            int r = er + mt * 16;
            int c = ec + nt * 8;
            *(float2*)&C[(size_t)r * N + c]       = make_float2(acc[mt][nt][0], acc[mt][nt][1]);
            *(float2*)&C[(size_t)(r + 8) * N + c] = make_float2(acc[mt][nt][2], acc[mt][nt][3]);
        }
}

// ---------------------------------------------------------------------------
// fp32 -> (hi, lo) bf16 split
// ---------------------------------------------------------------------------
__global__ __launch_bounds__(256)
void split_bf16(const float* __restrict__ in, __nv_bfloat16* __restrict__ hi,
                __nv_bfloat16* __restrict__ lo, int n4)
{
    int i = blockIdx.x * 256 + threadIdx.x;
    if (i >= n4) return;
    float4 v = ((const float4*)in)[i];
    __nv_bfloat16 h0 = __float2bfloat16(v.x), h1 = __float2bfloat16(v.y);
    __nv_bfloat16 h2 = __float2bfloat16(v.z), h3 = __float2bfloat16(v.w);
    __nv_bfloat162* hp = (__nv_bfloat162*)(hi + (size_t)i * 4);
    hp[0] = __nv_bfloat162(h0, h1);
    hp[1] = __nv_bfloat162(h2, h3);
    __nv_bfloat162* lp = (__nv_bfloat162*)(lo + (size_t)i * 4);
    lp[0] = __nv_bfloat162(__float2bfloat16(v.x - __bfloat162float(h0)),
                           __float2bfloat16(v.y - __bfloat162float(h1)));
    lp[1] = __nv_bfloat162(__float2bfloat16(v.z - __bfloat162float(h2)),
                           __float2bfloat16(v.w - __bfloat162float(h3)));
}

// ---------------------------------------------------------------------------
// fp32 tiled SGEMM (small GEMMs)
// ---------------------------------------------------------------------------
template<int BM, int BN, int BK, int TM, int TN, int EPI>
__global__ __launch_bounds__(256)
void sgemm_nt(const float* __restrict__ A, const float* __restrict__ W,
              float* __restrict__ C, int M, int N, int K, int lda,
              const float* __restrict__ bias,
              const float* __restrict__ lastscale)
{
    constexpr int NT = (BM / TM) * (BN / TN);
    static_assert(NT == 256, "need 256 threads");
    constexpr int LA = (BM * BK) / (4 * NT);
    constexpr int LB = (BN * BK) / (4 * NT);

    __shared__ __align__(16) float As[BK][BM];
    __shared__ __align__(16) float Bs[BK][BN];

    const int tid = threadIdx.x;
    const int bm = blockIdx.y * BM;
    const int bn = blockIdx.x * BN;
    const int tx = tid % (BN / TN);
    const int ty = tid / (BN / TN);

    float acc[TM][TN];
#pragma unroll
    for (int a = 0; a < TM; a++)
#pragma unroll
        for (int b = 0; b < TN; b++) acc[a][b] = 0.f;

    for (int k0 = 0; k0 < K; k0 += BK) {
#pragma unroll
        for (int l = 0; l < LA; l++) {
            int v = tid + l * NT;
            int r = v / (BK / 4);
            int kq = (v % (BK / 4)) * 4;
            int grow = bm + r;
            float4 av = make_float4(0.f, 0.f, 0.f, 0.f);
            if (grow < M)
                av = *(const float4*)(A + (size_t)grow * lda + k0 + kq);
            As[kq + 0][r] = av.x; As[kq + 1][r] = av.y;
            As[kq + 2][r] = av.z; As[kq + 3][r] = av.w;
        }
#pragma unroll
        for (int l = 0; l < LB; l++) {
            int v = tid + l * NT;
            int r = v / (BK / 4);
            int kq = (v % (BK / 4)) * 4;
            int gcol = bn + r;
            float4 wv = make_float4(0.f, 0.f, 0.f, 0.f);
            if (gcol < N)
                wv = *(const float4*)(W + (size_t)gcol * K + k0 + kq);
            Bs[kq + 0][r] = wv.x; Bs[kq + 1][r] = wv.y;
            Bs[kq + 2][r] = wv.z; Bs[kq + 3][r] = wv.w;
        }
        __syncthreads();

#pragma unroll
        for (int k = 0; k < BK; k++) {
            float ra[TM], rb[TN];
#pragma unroll
            for (int u = 0; u < TM / 4; u++)
                *(float4*)&ra[4 * u] = *(const float4*)&As[k][ty * TM + 4 * u];
#pragma unroll
            for (int u = 0; u < TN / 4; u++)
                *(float4*)&rb[4 * u] = *(const float4*)&Bs[k][tx * TN + 4 * u];
#pragma unroll
            for (int a = 0; a < TM; a++)
#pragma unroll
                for (int b = 0; b < TN; b++)
                    acc[a][b] = fmaf(ra[a], rb[b], acc[a][b]);
        }
        __syncthreads();
    }

#pragma unroll
    for (int a = 0; a < TM; a++) {
        int m = bm + ty * TM + a;
        if (m >= M) continue;
        bool last = ((m % Sl) == (Sl - 1));
#pragma unroll
        for (int b = 0; b < TN; b++) {
            int n = bn + tx * TN + b;
            if (n >= N) continue;
            float v = acc[a][b];
            if (EPI == 1) {
                v += bias[n];
                v = (v > 20.f) ? v : log1pf(__expf(v));
                if (last) v *= lastscale[n];
            }
            C[(size_t)m * N + n] = v;
        }
    }
}

// ---------------------------------------------------------------------------
// Causal depthwise conv1d (K=4) + bias + SiLU
// ---------------------------------------------------------------------------
__global__ __launch_bounds__(256)
void conv_silu_kernel(const float* __restrict__ proj,
                      const float* __restrict__ cw,
                      const float* __restrict__ cb,
                      float* __restrict__ h)
{
    const int bs = blockIdx.x;
    const int s = bs & (Sl - 1);
    for (int i = threadIdx.x; i < Iw; i += 256) {
        float4 w = *(const float4*)(cw + (size_t)i * 4);
        float acc = cb[i];
        const float* base = proj + (size_t)bs * TWO_I + i;
        if (s >= 3) acc = fmaf(w.x, base[-(size_t)3 * TWO_I], acc);
        if (s >= 2) acc = fmaf(w.y, base[-(size_t)2 * TWO_I], acc);
        if (s >= 1) acc = fmaf(w.z, base[-(size_t)1 * TWO_I], acc);
        acc = fmaf(w.w, base[0], acc);
        float sig = __fdividef(1.f, 1.f + __expf(-acc));
        h[(size_t)bs * Iw + i] = acc * sig;
    }
}

// ---------------------------------------------------------------------------
// Smem-staged selective scan, cp.async double-buffered.
// Block: 16 channels x 16 state-lanes = 256 threads; time chunk = 64 steps.
// Emits yhi/ylo bf16 split directly (fused epilogue: D, silu(gate), fg).
// ---------------------------------------------------------------------------
#define SCT 64                      // time steps per chunk
#define NCH (Sl / SCT)              // 32 chunks

__global__ __launch_bounds__(256)
void scan_kernel2(const float* __restrict__ dt,
                  const float* __restrict__ h,
                  const float* __restrict__ ssm,
                  const float* __restrict__ proj,
                  const float* __restrict__ A_log,
                  const float* __restrict__ Dv,
                  const float* __restrict__ fg,
                  __nv_bfloat16* __restrict__ yhi,
                  __nv_bfloat16* __restrict__ ylo)
{
    __shared__ __align__(16) float s_dt[2][SCT][16];
    __shared__ __align__(16) float s_h [2][SCT][16];
    __shared__ __align__(16) float s_g [2][SCT][16];
    __shared__ __align__(16) float s_B [2][SCT][16];
    __shared__ __align__(16) float s_C [2][SCT][16];
    __shared__ __align__(16) float s_y [SCT][16];
    __shared__ float s_D[16];

    const int tid = threadIdx.x;
    const int blk = blockIdx.x;                 // 0 .. B*I/16 - 1
    const int b = blk / (Iw / 16);
    const int i0 = (blk % (Iw / 16)) * 16;

    const int ci = tid >> 4;                    // channel within block
    const int ln = tid & 15;                    // state index

    if (tid < 16) s_D[tid] = Dv[i0 + tid];

    const float An = -__expf(A_log[(size_t)(i0 + ci) * Nst + ln]);
    float state = 0.f;

    const size_t row0 = (size_t)b * Sl;
    const int lr = tid >> 2, lc = (tid & 3) * 4;   // stage-load mapping

    const uint32_t a_dt = smem_u32(&s_dt[0][0][0]);
    const uint32_t a_h  = smem_u32(&s_h [0][0][0]);
    const uint32_t a_g  = smem_u32(&s_g [0][0][0]);
    const uint32_t a_B  = smem_u32(&s_B [0][0][0]);
    const uint32_t a_C  = smem_u32(&s_C [0][0][0]);
    const uint32_t stoff = SCT * 16 * 4;           // bytes per stage
    const uint32_t loff = (lr * 16 + lc) * 4;      // this thread's 16B slot

    auto issue = [&](int st, int s0) {
        size_t r = row0 + s0 + lr;
        cp16(a_dt + st * stoff + loff, dt   + r * Iw + i0 + lc);
        cp16(a_h  + st * stoff + loff, h    + r * Iw + i0 + lc);
        cp16(a_g  + st * stoff + loff, proj + r * TWO_I + Iw + i0 + lc);
        cp16(a_B  + st * stoff + loff, ssm  + r * (Rr + 2 * Nst) + Rr + lc);
        cp16(a_C  + st * stoff + loff, ssm  + r * (Rr + 2 * Nst) + Rr + Nst + lc);
        CP_COMMIT();
    };

    issue(0, 0);

    for (int ch = 0; ch < NCH; ch++) {
        const int st = ch & 1;
        const int s0 = ch * SCT;
        if (ch + 1 < NCH) { issue(st ^ 1, s0 + SCT); CP_WAIT(1); }
        else              { CP_WAIT(0); }
        __syncthreads();

        // sequential scan over this chunk; only serial dep is the state FMA
#pragma unroll 4
        for (int s = 0; s < SCT; s++) {
            float dtv = s_dt[st][s][ci];
            float hv  = s_h [st][s][ci];
            float dA  = __expf(An * dtv);
            state = fmaf(dA, state, dtv * s_B[st][s][ln] * hv);
            float part = state * s_C[st][s][ln];
            part += __shfl_xor_sync(0xffffffffu, part, 8);
            part += __shfl_xor_sync(0xffffffffu, part, 4);
            part += __shfl_xor_sync(0xffffffffu, part, 2);
            part += __shfl_xor_sync(0xffffffffu, part, 1);
            if (ln == 0) s_y[s][ci] = part;
        }
        __syncthreads();

        // parallel epilogue + bf16 split writeout
#pragma unroll
        for (int k = 0; k < 4; k++) {
            int idx = tid + k * 256;
            int r = idx >> 4, c = idx & 15;
            float hv = s_h[st][r][c];
            float g  = s_g[st][r][c];
            float sg = g * __fdividef(1.f, 1.f + __expf(-g));
            float val = (s_y[r][c] + hv * s_D[c]) * sg;
            if (s0 + r == Sl - 1) val *= fg[i0 + c];
            __nv_bfloat16 hi = __float2bfloat16(val);
            size_t o = (row0 + s0 + r) * Iw + i0 + c;
            yhi[o] = hi;
            ylo[o] = __float2bfloat16(val - __bfloat162float(hi));
        }
        __syncthreads();
    }
}

// ---------------------------------------------------------------------------
// Launch
// ---------------------------------------------------------------------------
extern "C" void kernel_launch(void* const* d_in, const int* in_sizes, int n_in,
                              void* d_out, int out_size)
{
    const float* x          = (const float*)d_in[0];
    const float* in_proj_w  = (const float*)d_in[1];
    const float* conv_w     = (const float*)d_in[2];
    const float* conv_b     = (const float*)d_in[3];
    const float* x_proj_w   = (const float*)d_in[4];
    const float* dt_proj_w  = (const float*)d_in[5];
    const float* dt_proj_b  = (const float*)d_in[6];
    const float* A_log      = (const float*)d_in[7];
    const float* Dv         = (const float*)d_in[8];
    const float* out_proj_w = (const float*)d_in[9];
    const float* alpha      = (const float*)d_in[10];
    const float* fg         = (const float*)d_in[11];
    float* out = (float*)d_out;

    float *proj, *h, *ssm, *dt;
    cudaGetSymbolAddress((void**)&proj, g_proj);
    cudaGetSymbolAddress((void**)&h,    g_h);
    cudaGetSymbolAddress((void**)&ssm,  g_ssm);
    cudaGetSymbolAddress((void**)&dt,   g_dt);

    __nv_bfloat16 *xhi, *xlo, *w1hi, *w1lo, *yhi, *ylo, *w2hi, *w2lo;
    cudaGetSymbolAddress((void**)&xhi,  g_xhi);
    cudaGetSymbolAddress((void**)&xlo,  g_xlo);
    cudaGetSymbolAddress((void**)&w1hi, g_w1hi);
    cudaGetSymbolAddress((void**)&w1lo, g_w1lo);
    cudaGetSymbolAddress((void**)&yhi,  g_yhi);
    cudaGetSymbolAddress((void**)&ylo,  g_ylo);
    cudaGetSymbolAddress((void**)&w2hi, g_w2hi);
    cudaGetSymbolAddress((void**)&w2lo, g_w2lo);

    cudaFuncSetAttribute(hmma_bf16x3, cudaFuncAttributeMaxDynamicSharedMemorySize, SMEM_B);

    // splits for in_proj
    {
        int n4 = (Ms * Dm) / 4;
        split_bf16<<<(n4 + 255) / 256, 256>>>(x, xhi, xlo, n4);
        n4 = (TWO_I * Dm) / 4;
        split_bf16<<<(n4 + 255) / 256, 256>>>(in_proj_w, w1hi, w1lo, n4);
    }

    // 1) in_proj (HMMA): proj[4096,3072] = x @ in_proj_w^T
    hmma_bf16x3<<<dim3(TWO_I / 128, Ms / 128), 256, SMEM_B>>>(
        xhi, xlo, w1hi, w1lo, proj, Ms, TWO_I, Dm);

    // 2) conv + SiLU
    conv_silu_kernel<<<Ms, 256>>>(proj, conv_w, conv_b, h);

    // 3) x_proj (fp32)
    sgemm_nt<64,64,16,4,4,0><<<dim3(2, Ms/64), 256>>>(
        h, x_proj_w, ssm, Ms, Rr + 2*Nst, Iw, Iw, nullptr, nullptr);

    // 4) dt_proj + softplus + alpha
    sgemm_nt<64,64,16,4,4,1><<<dim3(Iw/64, Ms/64), 256>>>(
        ssm, dt_proj_w, dt, Ms, Iw, Rr, Rr + 2*Nst, dt_proj_b, alpha);

    // 5) scan (smem-staged, emits bf16 split y directly)
    scan_kernel2<<<(Bsz * Iw) / 16, 256>>>(dt, h, ssm, proj, A_log, Dv, fg, yhi, ylo);

    // split out_proj weights
    {
        int n4 = (Dm * Iw) / 4;
        split_bf16<<<(n4 + 255) / 256, 256>>>(out_proj_w, w2hi, w2lo, n4);
    }

    // 6) out_proj (HMMA): out[4096,768] = y @ out_proj_w^T
    hmma_bf16x3<<<dim3(Dm / 128, Ms / 128), 256, SMEM_B>>>(
        yhi, ylo, w2hi, w2lo, out, Ms, Dm, Iw);
}